// round 13
// baseline (speedup 1.0000x reference)
#include <cuda_runtime.h>
#include <cuda_bf16.h>
#include <math.h>
#include <stdint.h>

constexpr int NB  = 4;
constexpr int NC  = 512;
constexpr int NHW = 4096;
constexpr int CAP = 1024;     // global list capacity per row
constexpr int CC  = 512;      // in-kernel candidate cap
#define EPSV 1e-5f

typedef __nv_bfloat16 bf16;

// ----------------------------- scratch (static; no allocation allowed) ----------
__device__ __align__(256) int8_t  g_E[(size_t)NB * NHW * NHW];                // 64MB s8
__device__ __align__(256) float   g_v[NB * NHW];
__device__ __align__(256) float   g_vb[NC];
__device__ __align__(256) float   g_ob2[NC];
__device__ __align__(256) float2  g_statC[NB * NC];
__device__ __align__(256) float2  g_statS[NB * NC];
__device__ __align__(256) int8_t  g_nCT_q[(size_t)NB * NHW * NC];             // 8MB s8
__device__ __align__(256) float   g_nCT_f[(size_t)NB * NHW * NC];             // 32MB
__device__ __align__(256) bf16    g_sT_h [(size_t)NB * NHW * NC], g_sT_l [(size_t)NB * NHW * NC];
__device__ __align__(256) int8_t  g_TT_q [(size_t)NB * NHW * NC];             // 8MB s8
__device__ __align__(256) float   g_TT_f [(size_t)NB * NHW * NC];             // 32MB
__device__ __align__(256) float   g_WoS  [(size_t)NB * NHW * NC];             // 32MB
__device__ __align__(256) ushort  g_lidx [(size_t)NB * NHW * CAP];            // 32MB
__device__ __align__(256) float   g_lw   [(size_t)NB * NHW * CAP];            // 64MB
__device__ __align__(256) int     g_lcnt [NB * NHW];
__device__ __align__(256) bf16    g_W1_h[NC * NC], g_W1_l[NC * NC];
__device__ __align__(256) bf16    g_Wo_h[NC * NC], g_Wo_l[NC * NC];
__device__ __align__(256) bf16    g_Bs_h[(size_t)NB * 2 * NC * NC];           // 4MB stacked B hi
__device__ __align__(256) bf16    g_Bs_l[(size_t)NB * 2 * NC * NC];           // 4MB stacked B lo

// ----------------------------- PTX helpers --------------------------------------
__device__ __forceinline__ uint32_t s2u(const void* p) {
    uint32_t a;
    asm("{ .reg .u64 t; cvta.to.shared.u64 t, %1; cvt.u32.u64 %0, t; }" : "=r"(a) : "l"(p));
    return a;
}
__device__ __forceinline__ void cpa16(uint32_t s, const void* g) {
    asm volatile("cp.async.cg.shared.global [%0], [%1], 16;" :: "r"(s), "l"(g));
}
__device__ __forceinline__ void cpa_commit() {
    asm volatile("cp.async.commit_group;" ::: "memory");
}
__device__ __forceinline__ void cpa_wait1() {
    asm volatile("cp.async.wait_group 1;" ::: "memory");
}
__device__ __forceinline__ void ldsm4(uint32_t a, uint32_t& r0, uint32_t& r1,
                                      uint32_t& r2, uint32_t& r3) {
    asm volatile("ldmatrix.sync.aligned.m8n8.x4.shared.b16 {%0,%1,%2,%3}, [%4];"
                 : "=r"(r0), "=r"(r1), "=r"(r2), "=r"(r3) : "r"(a));
}
__device__ __forceinline__ void mma_bf16(float* d, uint32_t a0, uint32_t a1, uint32_t a2,
                                         uint32_t a3, uint32_t b0, uint32_t b1) {
    asm volatile("mma.sync.aligned.m16n8k16.row.col.f32.bf16.bf16.f32 "
                 "{%0,%1,%2,%3}, {%4,%5,%6,%7}, {%8,%9}, {%0,%1,%2,%3};"
                 : "+f"(d[0]), "+f"(d[1]), "+f"(d[2]), "+f"(d[3])
                 : "r"(a0), "r"(a1), "r"(a2), "r"(a3), "r"(b0), "r"(b1));
}
__device__ __forceinline__ void mma_s8(float* d, uint32_t a0, uint32_t a1, uint32_t a2,
                                       uint32_t a3, uint32_t b0, uint32_t b1) {
    asm volatile("mma.sync.aligned.m16n8k32.row.col.s32.s8.s8.s32 "
                 "{%0,%1,%2,%3}, {%4,%5,%6,%7}, {%8,%9}, {%0,%1,%2,%3};"
                 : "+r"(*(int*)&d[0]), "+r"(*(int*)&d[1]),
                   "+r"(*(int*)&d[2]), "+r"(*(int*)&d[3])
                 : "r"(a0), "r"(a1), "r"(a2), "r"(a3), "r"(b0), "r"(b1));
}
__device__ __forceinline__ void split2(float v, ushort& h, ushort& l) {
    bf16 hb = __float2bfloat16(v);
    bf16 lb = __float2bfloat16(v - __bfloat162float(hb));
    h = __bfloat16_as_ushort(hb);
    l = __bfloat16_as_ushort(lb);
}
__device__ __forceinline__ int8_t to_s8(float v) {
    float q = fminf(fmaxf(v * 32.f, -127.f), 127.f);
    return (int8_t)__float2int_rn(q);
}
__device__ __forceinline__ uint8_t to_s8E(float v) {   // E screening quant: scale 1.25
    float q = fminf(fmaxf(v * 1.25f, -127.f), 127.f);
    return (uint8_t)(int8_t)__float2int_rn(q);
}

// ----------------------------- reductions ---------------------------------------
__device__ __forceinline__ float2 block_reduce_sum2(float s, float s2) {
    __shared__ float2 sh[8];
    int lane = threadIdx.x & 31, w = threadIdx.x >> 5;
    #pragma unroll
    for (int o = 16; o > 0; o >>= 1) {
        s  += __shfl_down_sync(0xffffffffu, s, o);
        s2 += __shfl_down_sync(0xffffffffu, s2, o);
    }
    if (lane == 0) sh[w] = make_float2(s, s2);
    __syncthreads();
    if (w == 0) {
        float2 v = (lane < 8) ? sh[lane] : make_float2(0.f, 0.f);
        #pragma unroll
        for (int o = 4; o > 0; o >>= 1) {
            v.x += __shfl_down_sync(0xffffffffu, v.x, o);
            v.y += __shfl_down_sync(0xffffffffu, v.y, o);
        }
        if (lane == 0) sh[0] = v;
    }
    __syncthreads();
    return sh[0];
}
__device__ __forceinline__ float block_reduce_max(float v) {
    __shared__ float sh[8];
    int lane = threadIdx.x & 31, w = threadIdx.x >> 5;
    #pragma unroll
    for (int o = 16; o > 0; o >>= 1) v = fmaxf(v, __shfl_down_sync(0xffffffffu, v, o));
    if (lane == 0) sh[w] = v;
    __syncthreads();
    if (w == 0) {
        float t = (lane < 8) ? sh[lane] : -3.4e38f;
        #pragma unroll
        for (int o = 4; o > 0; o >>= 1) t = fmaxf(t, __shfl_down_sync(0xffffffffu, t, o));
        if (lane == 0) sh[0] = t;
    }
    __syncthreads();
    return sh[0];
}
__device__ __forceinline__ float block_reduce_sum(float v) {
    __shared__ float sh[8];
    int lane = threadIdx.x & 31, w = threadIdx.x >> 5;
    #pragma unroll
    for (int o = 16; o > 0; o >>= 1) v += __shfl_down_sync(0xffffffffu, v, o);
    if (lane == 0) sh[w] = v;
    __syncthreads();
    if (w == 0) {
        float t = (lane < 8) ? sh[lane] : 0.f;
        #pragma unroll
        for (int o = 4; o > 0; o >>= 1) t += __shfl_down_sync(0xffffffffu, t, o);
        if (lane == 0) sh[0] = t;
    }
    __syncthreads();
    return sh[0];
}

// ----------------------------- stats: per (b,c) mean/rstd ------------------------
__global__ __launch_bounds__(256) void stats_kernel(const float* __restrict__ x,
                                                    float2* __restrict__ st) {
    size_t row = blockIdx.x;
    const float4* xp = (const float4*)(x + row * NHW);
    float s = 0.f, s2 = 0.f;
    #pragma unroll
    for (int i = 0; i < 4; i++) {
        float4 v = xp[threadIdx.x + i * 256];
        s  += v.x + v.y + v.z + v.w;
        s2 += v.x * v.x + v.y * v.y + v.z * v.z + v.w * v.w;
    }
    float2 r = block_reduce_sum2(s, s2);
    if (threadIdx.x == 0) {
        float mean = r.x * (1.f / NHW);
        float var  = r.y * (1.f / NHW) - mean * mean;
        st[row] = make_float2(mean, rsqrtf(var + EPSV));
    }
}

// ---------------- content transpose + norm: s8 + fp32 -----------------------------
__global__ __launch_bounds__(256) void tsplit_c_kernel(
    const float* __restrict__ x, const float2* __restrict__ st,
    int8_t* __restrict__ nq, float* __restrict__ nf)
{
    __shared__ float tile[32][33];
    int b  = blockIdx.z;
    int c0 = blockIdx.y * 32, q0 = blockIdx.x * 32;
    int tx = threadIdx.x & 31, ty = threadIdx.x >> 5;
    const float* xb = x + (size_t)b * NC * NHW;
    #pragma unroll
    for (int i = 0; i < 4; i++) {
        int cc = ty + 8 * i;
        tile[cc][tx] = xb[(size_t)(c0 + cc) * NHW + q0 + tx];
    }
    __syncthreads();
    int c = c0 + tx;
    float2 s = st[b * NC + c];
    #pragma unroll
    for (int i = 0; i < 4; i++) {
        int qq = ty + 8 * i;
        float v = tile[tx][qq];
        size_t o = (size_t)b * NHW * NC + (size_t)(q0 + qq) * NC + c;
        float nv = (v - s.x) * s.y;
        nq[o] = to_s8(nv);
        nf[o] = nv;
    }
}

// ---------------- style transpose: raw hi/lo only --------------------------------
__global__ __launch_bounds__(256) void tsplit_raw_kernel(
    const float* __restrict__ x,
    bf16* __restrict__ rh, bf16* __restrict__ rl)
{
    __shared__ float tile[32][33];
    int b  = blockIdx.z;
    int c0 = blockIdx.y * 32, q0 = blockIdx.x * 32;
    int tx = threadIdx.x & 31, ty = threadIdx.x >> 5;
    const float* xb = x + (size_t)b * NC * NHW;
    #pragma unroll
    for (int i = 0; i < 4; i++) {
        int cc = ty + 8 * i;
        tile[cc][tx] = xb[(size_t)(c0 + cc) * NHW + q0 + tx];
    }
    __syncthreads();
    #pragma unroll
    for (int i = 0; i < 4; i++) {
        int qq = ty + 8 * i;
        float v = tile[tx][qq];
        size_t o = (size_t)b * NHW * NC + (size_t)(q0 + qq) * NC + c0 + tx;
        ushort h, l;
        split2(v, h, l);
        rh[o] = __ushort_as_bfloat16(h);
        rl[o] = __ushort_as_bfloat16(l);
    }
}

// ---------------- small fp32 GEMM (512x512x512) -> bf16 split --------------------
template <int TA>
__global__ __launch_bounds__(256) void small_gemm_split(
    const float* __restrict__ A, const float* __restrict__ B,
    bf16* __restrict__ Dh, bf16* __restrict__ Dl)
{
    __shared__ float As[32][65];
    __shared__ float Bs[32][65];
    const int tid = threadIdx.x;
    const int i0 = blockIdx.y * 64, j0 = blockIdx.x * 64;
    const int ty = tid >> 4, tx = tid & 15;
    float acc[4][4] = {};
    for (int kc = 0; kc < NC; kc += 32) {
        if (TA) {
            int ii = tid & 63, kk = tid >> 6;
            #pragma unroll
            for (int p = 0; p < 8; p++)
                As[kk + 4 * p][ii] = A[(size_t)(kc + kk + 4 * p) * NC + i0 + ii];
        } else {
            int kk = tid & 31, ib = tid >> 5;
            #pragma unroll
            for (int p = 0; p < 8; p++)
                As[kk][ib + 8 * p] = A[(size_t)(i0 + ib + 8 * p) * NC + kc + kk];
        }
        {
            int jj = tid & 63, kk = tid >> 6;
            #pragma unroll
            for (int p = 0; p < 8; p++)
                Bs[kk + 4 * p][jj] = B[(size_t)(kc + kk + 4 * p) * NC + j0 + jj];
        }
        __syncthreads();
        #pragma unroll
        for (int k = 0; k < 32; k++) {
            float a[4], bv[4];
            #pragma unroll
            for (int u = 0; u < 4; u++) a[u]  = As[k][ty * 4 + u];
            #pragma unroll
            for (int u = 0; u < 4; u++) bv[u] = Bs[k][tx * 4 + u];
            #pragma unroll
            for (int u = 0; u < 4; u++)
                #pragma unroll
                for (int w = 0; w < 4; w++) acc[u][w] = fmaf(a[u], bv[w], acc[u][w]);
        }
        __syncthreads();
    }
    #pragma unroll
    for (int u = 0; u < 4; u++)
        #pragma unroll
        for (int w = 0; w < 4; w++) {
            size_t o = (size_t)(i0 + ty * 4 + u) * NC + j0 + tx * 4 + w;
            ushort h, l;
            split2(acc[u][w], h, l);
            Dh[o] = __ushort_as_bfloat16(h);
            Dl[o] = __ushort_as_bfloat16(l);
        }
}

// ---------------- build stacked B per batch: [Wo ; W1 * rstd] ---------------------
__global__ __launch_bounds__(256) void stack_kernel(
    const bf16* __restrict__ Woh, const bf16* __restrict__ Wol,
    const bf16* __restrict__ W1h, const bf16* __restrict__ W1l,
    const float2* __restrict__ stS,
    bf16* __restrict__ Bh, bf16* __restrict__ Bl)
{
    size_t t = (size_t)blockIdx.x * 256 + threadIdx.x;   // NB*1024*512 total
    int j = (int)(t & 511);
    size_t r = t >> 9;
    int i = (int)(r & 1023);
    int b = (int)(r >> 10);
    size_t o = ((size_t)b * 1024 + i) * 512 + j;
    if (i < 512) {
        Bh[o] = Woh[(size_t)i * 512 + j];
        Bl[o] = Wol[(size_t)i * 512 + j];
    } else {
        int ii = i - 512;
        float w = __bfloat162float(W1h[(size_t)ii * 512 + j]) +
                  __bfloat162float(W1l[(size_t)ii * 512 + j]);
        float sc = stS[b * 512 + j].y;
        ushort h, l;
        split2(w * sc, h, l);
        Bh[o] = __ushort_as_bfloat16(h);
        Bl[o] = __ushort_as_bfloat16(l);
    }
}

// ---------------- vb[j] = sum_c fb[c]*gw[c,j] ------------------------------------
__global__ __launch_bounds__(256) void vb_kernel(const float* __restrict__ fb,
                                                 const float* __restrict__ gw,
                                                 float* __restrict__ vb) {
    int j = blockIdx.x * 256 + threadIdx.x;
    float s = 0.f;
    for (int c = 0; c < NC; c++) s = fmaf(fb[c], gw[(size_t)c * NC + j], s);
    vb[j] = s;
}

// ---------------- v[b,s] = sum_j vb[j]*(style[b,j,s]-mean)*rstd -------------------
__global__ __launch_bounds__(256) void vrow_kernel(const float* __restrict__ style,
                                                   const float2* __restrict__ st,
                                                   const float* __restrict__ vb,
                                                   float* __restrict__ v) {
    int b = blockIdx.y;
    int s = blockIdx.x * 256 + threadIdx.x;
    const float* sb = style + (size_t)b * NC * NHW;
    float acc = 0.f;
    for (int j = 0; j < NC; j++) {
        float2 m = st[b * NC + j];
        acc = fmaf(vb[j], (sb[(size_t)j * NHW + s] - m.x) * m.y, acc);
    }
    v[b * NHW + s] = acc;
}

// ---------------- ob2[c] = sum_m o_w[c,m]*h_b[m] + o_b[c] ------------------------
__global__ __launch_bounds__(256) void ob2_kernel(const float* __restrict__ ow,
                                                  const float* __restrict__ hb,
                                                  const float* __restrict__ ob,
                                                  float* __restrict__ ob2) {
    int c = blockIdx.x * 256 + threadIdx.x;
    float s = ob[c];
    for (int m = 0; m < NC; m++) s = fmaf(ow[(size_t)c * NC + m], hb[m], s);
    ob2[c] = s;
}

// ---------------- sparse softmax with exact candidate recompute ------------------
// E is an int8-quantized int8-MMA approximation (decode step 0.8; combined noise
// ~0.38). Candidates = entries above approx-max - 16.3 (exact fp32 recompute via
// nCf . TTf). Band exp-sum only in (max-26, max-16.3].
__global__ __launch_bounds__(256) void softmax_sparse_kernel(
    const int8_t* __restrict__ Eq, const float* __restrict__ vrow,
    const float* __restrict__ nCf, const float* __restrict__ TTf,
    ushort* __restrict__ lidx, float* __restrict__ lw, int* __restrict__ lcnt)
{
    __shared__ float  s_nc[NC];
    __shared__ ushort s_idx[CC];
    __shared__ float  s_ex[CC];
    __shared__ int    wsum[8], wbase[8], s_n;
    const int b = blockIdx.y, q = blockIdx.x;
    const size_t rowid = (size_t)b * NHW + q;
    const size_t base  = rowid * NHW;
    const int tid = threadIdx.x, lane = tid & 31, w = tid >> 5;

    // load E row (16 s8 per thread) + v, decode, find approx max
    const int4* p = (const int4*)(Eq + base);
    int4 e4 = p[tid];
    const float4* vp = (const float4*)(vrow + (size_t)b * NHW) + tid * 4;
    float ev[16];
    {
        int wds[4] = {e4.x, e4.y, e4.z, e4.w};
        #pragma unroll
        for (int j = 0; j < 4; j++) {
            float4 vv = vp[j];
            int wd = wds[j];
            ev[4 * j + 0] = (float)((wd << 24) >> 24) * 0.8f + vv.x;
            ev[4 * j + 1] = (float)((wd << 16) >> 24) * 0.8f + vv.y;
            ev[4 * j + 2] = (float)((wd <<  8) >> 24) * 0.8f + vv.z;
            ev[4 * j + 3] = (float)( wd        >> 24) * 0.8f + vv.w;
        }
    }
    float mx = ev[0];
    #pragma unroll
    for (int j = 1; j < 16; j++) mx = fmaxf(mx, ev[j]);
    const float mxa = block_reduce_max(mx);
    const float T  = mxa - 16.3f;
    const float T2 = mxa - 26.0f;

    // load content row (fp32) into smem
    const float2* ncp = (const float2*)(nCf + rowid * NC);
    *(float2*)&s_nc[tid * 2] = ncp[tid];

    // candidate count + deterministic scan
    int cnt = 0;
    #pragma unroll
    for (int j = 0; j < 16; j++) cnt += (ev[j] > T);
    int incl = cnt;
    #pragma unroll
    for (int o = 1; o < 32; o <<= 1) {
        int n = __shfl_up_sync(0xffffffffu, incl, o);
        if (lane >= o) incl += n;
    }
    if (lane == 31) wsum[w] = incl;
    __syncthreads();
    if (tid == 0) {
        int r = 0;
        #pragma unroll
        for (int i = 0; i < 8; i++) { wbase[i] = r; r += wsum[i]; }
        s_n = (r < CC) ? r : CC;
    }
    __syncthreads();
    const int ncand = s_n;
    int k = wbase[w] + incl - cnt;

    // record candidate indices; band-limited non-candidate approx exp-sum
    float sn = 0.f;
    #pragma unroll
    for (int j = 0; j < 16; j++) {
        if (ev[j] > T) {
            if (k < CC) s_idx[k] = (ushort)(tid * 16 + j);
            k++;
        } else if (ev[j] > T2) {
            sn += __expf(ev[j] - mxa);
        }
    }
    const float Snon = block_reduce_sum(sn);

    // exact recompute: one warp per candidate
    for (int c = w; c < ncand; c += 8) {
        const int sidx = s_idx[c];
        const float4* tt = (const float4*)(TTf + ((size_t)b * NHW + sidx) * NC);
        float acc = 0.f;
        #pragma unroll
        for (int u = 0; u < 4; u++) {
            float4 t4 = tt[lane + 32 * u];
            const int o = (lane + 32 * u) * 4;
            acc = fmaf(t4.x, s_nc[o], acc);
            acc = fmaf(t4.y, s_nc[o + 1], acc);
            acc = fmaf(t4.z, s_nc[o + 2], acc);
            acc = fmaf(t4.w, s_nc[o + 3], acc);
        }
        #pragma unroll
        for (int o = 16; o > 0; o >>= 1) acc += __shfl_down_sync(0xffffffffu, acc, o);
        if (lane == 0) s_ex[c] = acc + vrow[(size_t)b * NHW + sidx];
    }
    __syncthreads();

    // denominator: banded non-candidates (approx) + candidates (exact)
    float cs = 0.f;
    for (int c = tid; c < ncand; c += 256) cs += __expf(s_ex[c] - mxa);
    const float Scand = block_reduce_sum(cs);
    const float inv = 1.0f / (Snon + Scand);

    // emit all candidates
    ushort* ip = lidx + rowid * CAP;
    float*  wp = lw   + rowid * CAP;
    for (int c = tid; c < ncand; c += 256) {
        ip[c] = s_idx[c];
        wp[c] = __expf(s_ex[c] - mxa) * inv;
    }
    if (tid == 0) lcnt[rowid] = ncand;
}

// ---------------- sparse apply: out[c,q] = ob2 + content + sum_k w*WoS[s_k,c] ----
__global__ __launch_bounds__(256) void sparse_apply_kernel(
    const float* __restrict__ WoS, const ushort* __restrict__ lidx,
    const float* __restrict__ lw, const int* __restrict__ lcnt,
    const float* __restrict__ ob2, const float* __restrict__ content,
    float* __restrict__ out)
{
    extern __shared__ float sacc[];   // [512][33]
    const int b = blockIdx.y, q0 = blockIdx.x * 32;
    const int tid = threadIdx.x, wid = tid >> 5, lane = tid & 31;
    const float* WoSb = WoS + (size_t)b * NHW * NC;

    #pragma unroll 1
    for (int j = 0; j < 4; j++) {
        const int q = q0 + wid * 4 + j;
        const size_t row = (size_t)b * NHW + q;
        const int cnt = lcnt[row];
        const ushort* ip = lidx + row * CAP;
        const float*  wp = lw   + row * CAP;
        float4 acc[4] = {};
        for (int k = 0; k < cnt; k++) {
            const int s = ip[k];
            const float wgt = wp[k];
            const float4* src = (const float4*)(WoSb + (size_t)s * NC) + lane;
            #pragma unroll
            for (int u = 0; u < 4; u++) {
                float4 vv = src[u * 32];
                acc[u].x = fmaf(wgt, vv.x, acc[u].x);
                acc[u].y = fmaf(wgt, vv.y, acc[u].y);
                acc[u].z = fmaf(wgt, vv.z, acc[u].z);
                acc[u].w = fmaf(wgt, vv.w, acc[u].w);
            }
        }
        const int qq = q - q0;
        #pragma unroll
        for (int u = 0; u < 4; u++) {
            const int c = lane * 4 + u * 128;
            sacc[(c + 0) * 33 + qq] = acc[u].x;
            sacc[(c + 1) * 33 + qq] = acc[u].y;
            sacc[(c + 2) * 33 + qq] = acc[u].z;
            sacc[(c + 3) * 33 + qq] = acc[u].w;
        }
    }
    __syncthreads();

    const float* cb = content + (size_t)b * NC * NHW;
    float* ob = out + (size_t)b * NC * NHW;
    #pragma unroll 1
    for (int p = 0; p < 16; p++) {
        const int c  = p * 32 + (tid >> 3);
        const int ch = (tid & 7) * 4;
        const float bias = ob2[c];
        float4 vv;
        vv.x = sacc[c * 33 + ch + 0] + bias;
        vv.y = sacc[c * 33 + ch + 1] + bias;
        vv.z = sacc[c * 33 + ch + 2] + bias;
        vv.w = sacc[c * 33 + ch + 3] + bias;
        const size_t o = (size_t)c * NHW + q0 + ch;
        const float4 cv = *(const float4*)(cb + o);
        vv.x += cv.x; vv.y += cv.y; vv.z += cv.z; vv.w += cv.w;
        *(float4*)(ob + o) = vv;
    }
}

// ---------------- 256x128 mma.sync GEMM ------------------------------------------
// NMMA 3: bf16 hi/lo 3-MMA split (K-step = 32 bf16 = 64B).
// NMMA 9: s8 single MMA m16n8k32, s32 accum (K-step = 64 s8 = 64B).
// SPLIT 4: merged N=1024: cols [0,512) -> Cf (WoS fp32); cols [512,1024) -> Cf2
//          (TTf fp32) + Cq (TT int8, scale 32). Output row stride = 512 each.
// SPLIT 5: C int8 (E screening: value = acc/1024, stored with scale 1.25).
constexpr int ATB = 16384;           // 256 rows x 64B component
constexpr int BTB = 8192;            // 128 rows x 64B component
constexpr int NSTG = 3;

__device__ __forceinline__ uint32_t swz(int r, int c) {
    return (uint32_t)(r * 64 + ((c ^ ((r >> 1) & 3)) << 4));
}

template <int NMMA, int SPLIT>
__global__ __launch_bounds__(512, 1) void mma_gemm(
    const void* __restrict__ Ahi, const void* __restrict__ Alo,
    const void* __restrict__ Bhi, const void* __restrict__ Blo,
    float* __restrict__ Cf, float* __restrict__ Cf2,
    int8_t* __restrict__ Cq,
    int M, int N, int K,
    long sA, long sB, long sC)
{
    constexpr int ES     = (NMMA == 9) ? 1 : 2;
    constexpr int STGB   = (NMMA == 3) ? (2 * ATB + 2 * BTB) : (ATB + BTB);
    constexpr int OFF_BH = (NMMA == 3) ? 2 * ATB : ATB;

    extern __shared__ __align__(128) char dsm[];
    const uint32_t smb = s2u(dsm);

    const int tid = threadIdx.x, wid = tid >> 5, lane = tid & 31;
    const int m0 = blockIdx.y * 256, n0 = blockIdx.x * 128, b = blockIdx.z;
    const int warpM = wid & 3, warpN = wid >> 2;
    const int KT = (K * ES) / 64;          // K-steps of 64 bytes

    const int rA = tid >> 1, cA = (tid & 1) * 2;
    const int rB = tid >> 2, cB = tid & 3;
    const uint8_t* pAh = (const uint8_t*)Ahi + ((size_t)b * sA + (size_t)(m0 + rA) * K) * ES + cA * 16;
    const uint8_t* pAl = (NMMA == 3) ?
        (const uint8_t*)Alo + ((size_t)b * sA + (size_t)(m0 + rA) * K) * ES + cA * 16 : nullptr;
    const uint8_t* pBh = (const uint8_t*)Bhi + ((size_t)b * sB + (size_t)(n0 + rB) * K) * ES + cB * 16;
    const uint8_t* pBl = (NMMA == 3) ?
        (const uint8_t*)Blo + ((size_t)b * sB + (size_t)(n0 + rB) * K) * ES + cB * 16 : nullptr;
    const uint32_t dA0 = swz(rA, cA), dA1 = swz(rA, cA + 1);
    const uint32_t dB  = swz(rB, cB);

    auto load_stage = [&](int s, int k0b) {
        const uint32_t sb = smb + s * STGB;
        cpa16(sb + dA0, pAh + k0b);
        cpa16(sb + dA1, pAh + k0b + 16);
        if (NMMA == 3) {
            cpa16(sb + ATB + dA0, pAl + k0b);
            cpa16(sb + ATB + dA1, pAl + k0b + 16);
        }
        cpa16(sb + OFF_BH + dB, pBh + k0b);
        if (NMMA == 3) cpa16(sb + OFF_BH + BTB + dB, pBl + k0b);
    };

    float acc[4][4][4];
    #pragma unroll
    for (int i = 0; i < 4; i++)
        #pragma unroll
        for (int j = 0; j < 4; j++)
            #pragma unroll
            for (int q = 0; q < 4; q++) acc[i][j][q] = 0.f;   // 0.0f bits == int 0

    load_stage(0, 0);  cpa_commit();
    load_stage(1, 64); cpa_commit();

    const int arow = warpM * 64 + (lane & 15);
    const int brow = warpN * 32 + (lane & 15);

    for (int kt = 0; kt < KT; kt++) {
        cpa_wait1();
        __syncthreads();
        const int cur = kt % NSTG;
        if (kt + 2 < KT) load_stage((kt + 2) % NSTG, (kt + 2) * 64);
        cpa_commit();

        const uint32_t sAh = smb + cur * STGB;
        const uint32_t sAl = sAh + ATB;
        const uint32_t sBh = sAh + OFF_BH;
        const uint32_t sBl = sBh + BTB;

        #pragma unroll
        for (int kk = 0; kk < 2; kk++) {
            const int ch = kk * 2 + (lane >> 4);
            uint32_t ah[4][4], al[4][4];
            #pragma unroll
            for (int mi = 0; mi < 4; mi++) {
                uint32_t off = swz(arow + mi * 16, ch);
                ldsm4(sAh + off, ah[mi][0], ah[mi][1], ah[mi][2], ah[mi][3]);
                if (NMMA == 3)
                    ldsm4(sAl + off, al[mi][0], al[mi][1], al[mi][2], al[mi][3]);
            }
            #pragma unroll
            for (int g = 0; g < 2; g++) {
                uint32_t off = swz(brow + g * 16, ch);
                uint32_t h0, h1, h2, h3, l0, l1, l2, l3;
                ldsm4(sBh + off, h0, h1, h2, h3);
                if (NMMA == 3) ldsm4(sBl + off, l0, l1, l2, l3);
                #pragma unroll
                for (int mi = 0; mi < 4; mi++) {
                    if (NMMA == 9) {
                        mma_s8(acc[mi][2 * g],     ah[mi][0], ah[mi][1], ah[mi][2], ah[mi][3], h0, h2);
                        mma_s8(acc[mi][2 * g + 1], ah[mi][0], ah[mi][1], ah[mi][2], ah[mi][3], h1, h3);
                    } else {
                        mma_bf16(acc[mi][2 * g],     ah[mi][0], ah[mi][1], ah[mi][2], ah[mi][3], h0, h2);
                        mma_bf16(acc[mi][2 * g],     ah[mi][0], ah[mi][1], ah[mi][2], ah[mi][3], l0, l2);
                        mma_bf16(acc[mi][2 * g],     al[mi][0], al[mi][1], al[mi][2], al[mi][3], h0, h2);
                        mma_bf16(acc[mi][2 * g + 1], ah[mi][0], ah[mi][1], ah[mi][2], ah[mi][3], h1, h3);
                        mma_bf16(acc[mi][2 * g + 1], ah[mi][0], ah[mi][1], ah[mi][2], ah[mi][3], l1, l3);
                        mma_bf16(acc[mi][2 * g + 1], al[mi][0], al[mi][1], al[mi][2], al[mi][3], h1, h3);
                    }
                }
            }
        }
        __syncthreads();
    }

    // ---------------- epilogue -------------------------------------------------
    #pragma unroll
    for (int mi = 0; mi < 4; mi++) {
        const int r0 = m0 + warpM * 64 + mi * 16 + (lane >> 2);
        #pragma unroll
        for (int j = 0; j < 4; j++) {
            const int col = n0 + warpN * 32 + j * 8 + (lane & 3) * 2;
            float v[4];
            #pragma unroll
            for (int q = 0; q < 4; q++) {
                if (NMMA == 9) v[q] = (float)(*(int*)&acc[mi][j][q]) * (1.f / 1024.f);
                else           v[q] = acc[mi][j][q];
            }
            if (SPLIT == 5) {
                const size_t o0 = (size_t)b * sC + (size_t)r0 * N + col;
                const size_t o1 = o0 + (size_t)8 * N;
                *(ushort*)(Cq + o0) = (ushort)to_s8E(v[0]) | ((ushort)to_s8E(v[1]) << 8);
                *(ushort*)(Cq + o1) = (ushort)to_s8E(v[2]) | ((ushort)to_s8E(v[3]) << 8);
            } else {  // SPLIT == 4: merged output
                if (col < 512) {
                    const size_t o0 = (size_t)b * sC + (size_t)r0 * 512 + col;
                    const size_t o1 = o0 + (size_t)8 * 512;
                    *(float2*)(Cf + o0) = make_float2(v[0], v[1]);
                    *(float2*)(Cf + o1) = make_float2(v[2], v[3]);
                } else {
                    const int c2 = col - 512;
                    const size_t o0 = (size_t)b * sC + (size_t)r0 * 512 + c2;
                    const size_t o1 = o0 + (size_t)8 * 512;
                    *(float2*)(Cf2 + o0) = make_float2(v[0], v[1]);
                    *(float2*)(Cf2 + o1) = make_float2(v[2], v[3]);
                    uint8_t a0 = (uint8_t)to_s8(v[0]), a1 = (uint8_t)to_s8(v[1]);
                    *(ushort*)(Cq + o0) = (ushort)a0 | ((ushort)a1 << 8);
                    a0 = (uint8_t)to_s8(v[2]); a1 = (uint8_t)to_s8(v[3]);
                    *(ushort*)(Cq + o1) = (ushort)a0 | ((ushort)a1 << 8);
                }
            }
        }
    }
}

constexpr int DSMEM3 = NSTG * (2 * ATB + 2 * BTB);  // 144 KB
constexpr int DSMEM9 = NSTG * (ATB + BTB);          // 72 KB

// ----------------------------- launch --------------------------------------------
extern "C" void kernel_launch(void* const* d_in, const int* in_sizes, int n_in,
                              void* d_out, int out_size) {
    const float* content = (const float*)d_in[0];
    const float* style   = (const float*)d_in[1];
    const float* f_w = (const float*)d_in[2];
    const float* f_b = (const float*)d_in[3];
    const float* g_w = (const float*)d_in[4];
    const float* h_w = (const float*)d_in[6];
    const float* h_b = (const float*)d_in[7];
    const float* o_w = (const float*)d_in[8];
    const float* o_b = (const float*)d_in[9];
    float* out = (float*)d_out;

    float *v, *vb, *ob2, *WoS, *lwp, *nCf, *TTf; float2 *stC, *stS;
    bf16 *sTh, *sTl, *W1h, *W1l, *Woh, *Wol, *Bh, *Bl;
    int8_t *E, *nCq, *TTq;
    ushort *lip; int *lcp;
    cudaGetSymbolAddress((void**)&E,   g_E);
    cudaGetSymbolAddress((void**)&v,   g_v);
    cudaGetSymbolAddress((void**)&vb,  g_vb);
    cudaGetSymbolAddress((void**)&ob2, g_ob2);
    cudaGetSymbolAddress((void**)&WoS, g_WoS);
    cudaGetSymbolAddress((void**)&stC, g_statC);
    cudaGetSymbolAddress((void**)&stS, g_statS);
    cudaGetSymbolAddress((void**)&nCq,  g_nCT_q);
    cudaGetSymbolAddress((void**)&nCf,  g_nCT_f);
    cudaGetSymbolAddress((void**)&sTh,  g_sT_h);  cudaGetSymbolAddress((void**)&sTl,  g_sT_l);
    cudaGetSymbolAddress((void**)&TTq,  g_TT_q);
    cudaGetSymbolAddress((void**)&TTf,  g_TT_f);
    cudaGetSymbolAddress((void**)&W1h,  g_W1_h);  cudaGetSymbolAddress((void**)&W1l,  g_W1_l);
    cudaGetSymbolAddress((void**)&Woh,  g_Wo_h);  cudaGetSymbolAddress((void**)&Wol,  g_Wo_l);
    cudaGetSymbolAddress((void**)&Bh,   g_Bs_h);  cudaGetSymbolAddress((void**)&Bl,   g_Bs_l);
    cudaGetSymbolAddress((void**)&lip,  g_lidx);
    cudaGetSymbolAddress((void**)&lwp,  g_lw);
    cudaGetSymbolAddress((void**)&lcp,  g_lcnt);

    cudaFuncSetAttribute(mma_gemm<3,4>, cudaFuncAttributeMaxDynamicSharedMemorySize, DSMEM3);
    cudaFuncSetAttribute(mma_gemm<9,5>, cudaFuncAttributeMaxDynamicSharedMemorySize, DSMEM9);
    cudaFuncSetAttribute(sparse_apply_kernel, cudaFuncAttributeMaxDynamicSharedMemorySize, 512 * 33 * 4);

    const long sQC = (long)NHW * NC;    // [B, 4096, 512]
    const long sBK = (long)2 * NC * NC; // stacked B per-batch stride (1024x512)
    const long sE  = (long)NHW * NHW;

    // 1) stats
    stats_kernel<<<NB * NC, 256>>>(content, stC);
    stats_kernel<<<NB * NC, 256>>>(style,   stS);

    // 2) transposed operands
    dim3 gt(NHW / 32, NC / 32, NB);
    tsplit_c_kernel<<<gt, 256>>>(content, stC, nCq, nCf);
    tsplit_raw_kernel<<<gt, 256>>>(style, sTh, sTl);

    // 3) folded weights: W1 = fw^T gw, Wo = o_w h_w; stacked B; bias vectors
    dim3 gw64(NC / 64, NC / 64);
    small_gemm_split<1><<<gw64, 256>>>(f_w, g_w, W1h, W1l);
    small_gemm_split<0><<<gw64, 256>>>(o_w, h_w, Woh, Wol);
    stack_kernel<<<(unsigned)((size_t)NB * 2 * NC * NC / 256), 256>>>(
        Woh, Wol, W1h, W1l, stS, Bh, Bl);
    vb_kernel<<<NC / 256, 256>>>(f_b, g_w, vb);
    vrow_kernel<<<dim3(NHW / 256, NB), 256>>>(style, stS, vb, v);
    ob2_kernel<<<NC / 256, 256>>>(o_w, h_b, o_b, ob2);

    // 4) merged: [WoS | TT] = sT x [Wo ; W1*rstd]^T  (M=4096, N=1024, K=512)
    dim3 gM(2 * NC / 128, NHW / 256, NB);   // (8, 16, 4)
    mma_gemm<3,4><<<gM, 512, DSMEM3>>>(sTh, sTl, Bh, Bl,
                                       WoS, TTf, TTq,
                                       NHW, 2 * NC, NC, sQC, sBK, sQC);

    // 5) E approx[q,s] (int8 1-MMA), int8 out (scale 1.25, step 0.8)
    dim3 gE(NHW / 128, NHW / 256, NB);      // (32, 16, 4)
    mma_gemm<9,5><<<gE, 512, DSMEM9>>>(nCq, nullptr, TTq, nullptr,
                                       nullptr, nullptr, E,
                                       NHW, NHW, NC, sQC, sQC, sE);

    // 6) sparse softmax: candidates from approx E (int8), exact fp32 recompute
    dim3 gs(NHW, NB);
    softmax_sparse_kernel<<<gs, 256>>>(E, v, nCf, TTf, lip, lwp, lcp);

    // 7) sparse apply: out[c,q] = ob2[c] + content[c,q] + sum w * WoS[s,c]
    dim3 ga(NHW / 32, NB);
    sparse_apply_kernel<<<ga, 256, 512 * 33 * 4>>>(WoS, lip, lwp, lcp, ob2, content, out);
}

// round 14
// speedup vs baseline: 1.0214x; 1.0214x over previous
#include <cuda_runtime.h>
#include <cuda_bf16.h>
#include <math.h>
#include <stdint.h>

constexpr int NB  = 4;
constexpr int NC  = 512;
constexpr int NHW = 4096;
constexpr int CAP = 1024;     // global list capacity per row
constexpr int CC  = 512;      // in-kernel candidate cap
#define EPSV 1e-5f

typedef __nv_bfloat16 bf16;

// ----------------------------- scratch (static; no allocation allowed) ----------
__device__ __align__(256) int8_t  g_E[(size_t)NB * NHW * NHW];                // 64MB s8
__device__ __align__(256) float   g_v[NB * NHW];
__device__ __align__(256) float   g_vb[NC];
__device__ __align__(256) float   g_ob2[NC];
__device__ __align__(256) float2  g_statC[NB * NC];
__device__ __align__(256) float2  g_statS[NB * NC];
__device__ __align__(256) int8_t  g_nCT_q[(size_t)NB * NHW * NC];             // 8MB s8
__device__ __align__(256) float   g_nCT_f[(size_t)NB * NHW * NC];             // 32MB
__device__ __align__(256) bf16    g_sT_h [(size_t)NB * NHW * NC], g_sT_l [(size_t)NB * NHW * NC];
__device__ __align__(256) int8_t  g_TT_q [(size_t)NB * NHW * NC];             // 8MB s8
__device__ __align__(256) float   g_TT_f [(size_t)NB * NHW * NC];             // 32MB
__device__ __align__(256) float   g_WoS  [(size_t)NB * NHW * NC];             // 32MB
__device__ __align__(256) ushort  g_lidx [(size_t)NB * NHW * CAP];            // 32MB
__device__ __align__(256) float   g_lw   [(size_t)NB * NHW * CAP];            // 64MB
__device__ __align__(256) int     g_lcnt [NB * NHW];
__device__ __align__(256) bf16    g_W1_h[NC * NC], g_W1_l[NC * NC];
__device__ __align__(256) bf16    g_Wo_h[NC * NC], g_Wo_l[NC * NC];
__device__ __align__(256) bf16    g_Bs_h[(size_t)NB * 2 * NC * NC];           // 4MB stacked B hi
__device__ __align__(256) bf16    g_Bs_l[(size_t)NB * 2 * NC * NC];           // 4MB stacked B lo

// ----------------------------- PTX helpers --------------------------------------
__device__ __forceinline__ uint32_t s2u(const void* p) {
    uint32_t a;
    asm("{ .reg .u64 t; cvta.to.shared.u64 t, %1; cvt.u32.u64 %0, t; }" : "=r"(a) : "l"(p));
    return a;
}
__device__ __forceinline__ void cpa16(uint32_t s, const void* g) {
    asm volatile("cp.async.cg.shared.global [%0], [%1], 16;" :: "r"(s), "l"(g));
}
__device__ __forceinline__ void cpa_commit() {
    asm volatile("cp.async.commit_group;" ::: "memory");
}
__device__ __forceinline__ void cpa_wait1() {
    asm volatile("cp.async.wait_group 1;" ::: "memory");
}
__device__ __forceinline__ void cpa_wait0() {
    asm volatile("cp.async.wait_group 0;" ::: "memory");
}
__device__ __forceinline__ void ldsm4(uint32_t a, uint32_t& r0, uint32_t& r1,
                                      uint32_t& r2, uint32_t& r3) {
    asm volatile("ldmatrix.sync.aligned.m8n8.x4.shared.b16 {%0,%1,%2,%3}, [%4];"
                 : "=r"(r0), "=r"(r1), "=r"(r2), "=r"(r3) : "r"(a));
}
__device__ __forceinline__ void mma_bf16(float* d, uint32_t a0, uint32_t a1, uint32_t a2,
                                         uint32_t a3, uint32_t b0, uint32_t b1) {
    asm volatile("mma.sync.aligned.m16n8k16.row.col.f32.bf16.bf16.f32 "
                 "{%0,%1,%2,%3}, {%4,%5,%6,%7}, {%8,%9}, {%0,%1,%2,%3};"
                 : "+f"(d[0]), "+f"(d[1]), "+f"(d[2]), "+f"(d[3])
                 : "r"(a0), "r"(a1), "r"(a2), "r"(a3), "r"(b0), "r"(b1));
}
__device__ __forceinline__ void mma_s8(float* d, uint32_t a0, uint32_t a1, uint32_t a2,
                                       uint32_t a3, uint32_t b0, uint32_t b1) {
    asm volatile("mma.sync.aligned.m16n8k32.row.col.s32.s8.s8.s32 "
                 "{%0,%1,%2,%3}, {%4,%5,%6,%7}, {%8,%9}, {%0,%1,%2,%3};"
                 : "+r"(*(int*)&d[0]), "+r"(*(int*)&d[1]),
                   "+r"(*(int*)&d[2]), "+r"(*(int*)&d[3])
                 : "r"(a0), "r"(a1), "r"(a2), "r"(a3), "r"(b0), "r"(b1));
}
__device__ __forceinline__ void split2(float v, ushort& h, ushort& l) {
    bf16 hb = __float2bfloat16(v);
    bf16 lb = __float2bfloat16(v - __bfloat162float(hb));
    h = __bfloat16_as_ushort(hb);
    l = __bfloat16_as_ushort(lb);
}
__device__ __forceinline__ int8_t to_s8(float v) {
    float q = fminf(fmaxf(v * 32.f, -127.f), 127.f);
    return (int8_t)__float2int_rn(q);
}
__device__ __forceinline__ int8_t to_s8E(float v) {    // E screening quant: scale 1.25
    float q = fminf(fmaxf(v * 1.25f, -127.f), 127.f);
    return (int8_t)__float2int_rn(q);
}

// ----------------------------- reductions ---------------------------------------
__device__ __forceinline__ float2 block_reduce_sum2(float s, float s2) {
    __shared__ float2 sh[8];
    int lane = threadIdx.x & 31, w = threadIdx.x >> 5;
    #pragma unroll
    for (int o = 16; o > 0; o >>= 1) {
        s  += __shfl_down_sync(0xffffffffu, s, o);
        s2 += __shfl_down_sync(0xffffffffu, s2, o);
    }
    if (lane == 0) sh[w] = make_float2(s, s2);
    __syncthreads();
    if (w == 0) {
        float2 v = (lane < 8) ? sh[lane] : make_float2(0.f, 0.f);
        #pragma unroll
        for (int o = 4; o > 0; o >>= 1) {
            v.x += __shfl_down_sync(0xffffffffu, v.x, o);
            v.y += __shfl_down_sync(0xffffffffu, v.y, o);
        }
        if (lane == 0) sh[0] = v;
    }
    __syncthreads();
    return sh[0];
}
__device__ __forceinline__ float block_reduce_max(float v) {
    __shared__ float sh[8];
    int lane = threadIdx.x & 31, w = threadIdx.x >> 5;
    #pragma unroll
    for (int o = 16; o > 0; o >>= 1) v = fmaxf(v, __shfl_down_sync(0xffffffffu, v, o));
    if (lane == 0) sh[w] = v;
    __syncthreads();
    if (w == 0) {
        float t = (lane < 8) ? sh[lane] : -3.4e38f;
        #pragma unroll
        for (int o = 4; o > 0; o >>= 1) t = fmaxf(t, __shfl_down_sync(0xffffffffu, t, o));
        if (lane == 0) sh[0] = t;
    }
    __syncthreads();
    return sh[0];
}
__device__ __forceinline__ float block_reduce_sum(float v) {
    __shared__ float sh[8];
    int lane = threadIdx.x & 31, w = threadIdx.x >> 5;
    #pragma unroll
    for (int o = 16; o > 0; o >>= 1) v += __shfl_down_sync(0xffffffffu, v, o);
    if (lane == 0) sh[w] = v;
    __syncthreads();
    if (w == 0) {
        float t = (lane < 8) ? sh[lane] : 0.f;
        #pragma unroll
        for (int o = 4; o > 0; o >>= 1) t += __shfl_down_sync(0xffffffffu, t, o);
        if (lane == 0) sh[0] = t;
    }
    __syncthreads();
    return sh[0];
}

// ----------------------------- stats: per (b,c) mean/rstd ------------------------
__global__ __launch_bounds__(256) void stats_kernel(const float* __restrict__ x,
                                                    float2* __restrict__ st) {
    size_t row = blockIdx.x;
    const float4* xp = (const float4*)(x + row * NHW);
    float s = 0.f, s2 = 0.f;
    #pragma unroll
    for (int i = 0; i < 4; i++) {
        float4 v = xp[threadIdx.x + i * 256];
        s  += v.x + v.y + v.z + v.w;
        s2 += v.x * v.x + v.y * v.y + v.z * v.z + v.w * v.w;
    }
    float2 r = block_reduce_sum2(s, s2);
    if (threadIdx.x == 0) {
        float mean = r.x * (1.f / NHW);
        float var  = r.y * (1.f / NHW) - mean * mean;
        st[row] = make_float2(mean, rsqrtf(var + EPSV));
    }
}

// ---------------- content transpose + norm: s8 + fp32 -----------------------------
__global__ __launch_bounds__(256) void tsplit_c_kernel(
    const float* __restrict__ x, const float2* __restrict__ st,
    int8_t* __restrict__ nq, float* __restrict__ nf)
{
    __shared__ float tile[32][33];
    int b  = blockIdx.z;
    int c0 = blockIdx.y * 32, q0 = blockIdx.x * 32;
    int tx = threadIdx.x & 31, ty = threadIdx.x >> 5;
    const float* xb = x + (size_t)b * NC * NHW;
    #pragma unroll
    for (int i = 0; i < 4; i++) {
        int cc = ty + 8 * i;
        tile[cc][tx] = xb[(size_t)(c0 + cc) * NHW + q0 + tx];
    }
    __syncthreads();
    int c = c0 + tx;
    float2 s = st[b * NC + c];
    #pragma unroll
    for (int i = 0; i < 4; i++) {
        int qq = ty + 8 * i;
        float v = tile[tx][qq];
        size_t o = (size_t)b * NHW * NC + (size_t)(q0 + qq) * NC + c;
        float nv = (v - s.x) * s.y;
        nq[o] = to_s8(nv);
        nf[o] = nv;
    }
}

// ---------------- style transpose: raw hi/lo only --------------------------------
__global__ __launch_bounds__(256) void tsplit_raw_kernel(
    const float* __restrict__ x,
    bf16* __restrict__ rh, bf16* __restrict__ rl)
{
    __shared__ float tile[32][33];
    int b  = blockIdx.z;
    int c0 = blockIdx.y * 32, q0 = blockIdx.x * 32;
    int tx = threadIdx.x & 31, ty = threadIdx.x >> 5;
    const float* xb = x + (size_t)b * NC * NHW;
    #pragma unroll
    for (int i = 0; i < 4; i++) {
        int cc = ty + 8 * i;
        tile[cc][tx] = xb[(size_t)(c0 + cc) * NHW + q0 + tx];
    }
    __syncthreads();
    #pragma unroll
    for (int i = 0; i < 4; i++) {
        int qq = ty + 8 * i;
        float v = tile[tx][qq];
        size_t o = (size_t)b * NHW * NC + (size_t)(q0 + qq) * NC + c0 + tx;
        ushort h, l;
        split2(v, h, l);
        rh[o] = __ushort_as_bfloat16(h);
        rl[o] = __ushort_as_bfloat16(l);
    }
}

// ---------------- small fp32 GEMM (512x512x512) -> bf16 split --------------------
template <int TA>
__global__ __launch_bounds__(256) void small_gemm_split(
    const float* __restrict__ A, const float* __restrict__ B,
    bf16* __restrict__ Dh, bf16* __restrict__ Dl)
{
    __shared__ float As[32][65];
    __shared__ float Bs[32][65];
    const int tid = threadIdx.x;
    const int i0 = blockIdx.y * 64, j0 = blockIdx.x * 64;
    const int ty = tid >> 4, tx = tid & 15;
    float acc[4][4] = {};
    for (int kc = 0; kc < NC; kc += 32) {
        if (TA) {
            int ii = tid & 63, kk = tid >> 6;
            #pragma unroll
            for (int p = 0; p < 8; p++)
                As[kk + 4 * p][ii] = A[(size_t)(kc + kk + 4 * p) * NC + i0 + ii];
        } else {
            int kk = tid & 31, ib = tid >> 5;
            #pragma unroll
            for (int p = 0; p < 8; p++)
                As[kk][ib + 8 * p] = A[(size_t)(i0 + ib + 8 * p) * NC + kc + kk];
        }
        {
            int jj = tid & 63, kk = tid >> 6;
            #pragma unroll
            for (int p = 0; p < 8; p++)
                Bs[kk + 4 * p][jj] = B[(size_t)(kc + kk + 4 * p) * NC + j0 + jj];
        }
        __syncthreads();
        #pragma unroll
        for (int k = 0; k < 32; k++) {
            float a[4], bv[4];
            #pragma unroll
            for (int u = 0; u < 4; u++) a[u]  = As[k][ty * 4 + u];
            #pragma unroll
            for (int u = 0; u < 4; u++) bv[u] = Bs[k][tx * 4 + u];
            #pragma unroll
            for (int u = 0; u < 4; u++)
                #pragma unroll
                for (int w = 0; w < 4; w++) acc[u][w] = fmaf(a[u], bv[w], acc[u][w]);
        }
        __syncthreads();
    }
    #pragma unroll
    for (int u = 0; u < 4; u++)
        #pragma unroll
        for (int w = 0; w < 4; w++) {
            size_t o = (size_t)(i0 + ty * 4 + u) * NC + j0 + tx * 4 + w;
            ushort h, l;
            split2(acc[u][w], h, l);
            Dh[o] = __ushort_as_bfloat16(h);
            Dl[o] = __ushort_as_bfloat16(l);
        }
}

// ---------------- build stacked B per batch: [Wo ; W1 * rstd] ---------------------
__global__ __launch_bounds__(256) void stack_kernel(
    const bf16* __restrict__ Woh, const bf16* __restrict__ Wol,
    const bf16* __restrict__ W1h, const bf16* __restrict__ W1l,
    const float2* __restrict__ stS,
    bf16* __restrict__ Bh, bf16* __restrict__ Bl)
{
    size_t t = (size_t)blockIdx.x * 256 + threadIdx.x;   // NB*1024*512 total
    int j = (int)(t & 511);
    size_t r = t >> 9;
    int i = (int)(r & 1023);
    int b = (int)(r >> 10);
    size_t o = ((size_t)b * 1024 + i) * 512 + j;
    if (i < 512) {
        Bh[o] = Woh[(size_t)i * 512 + j];
        Bl[o] = Wol[(size_t)i * 512 + j];
    } else {
        int ii = i - 512;
        float w = __bfloat162float(W1h[(size_t)ii * 512 + j]) +
                  __bfloat162float(W1l[(size_t)ii * 512 + j]);
        float sc = stS[b * 512 + j].y;
        ushort h, l;
        split2(w * sc, h, l);
        Bh[o] = __ushort_as_bfloat16(h);
        Bl[o] = __ushort_as_bfloat16(l);
    }
}

// ---------------- vb[j] = sum_c fb[c]*gw[c,j] ------------------------------------
__global__ __launch_bounds__(256) void vb_kernel(const float* __restrict__ fb,
                                                 const float* __restrict__ gw,
                                                 float* __restrict__ vb) {
    int j = blockIdx.x * 256 + threadIdx.x;
    float s = 0.f;
    for (int c = 0; c < NC; c++) s = fmaf(fb[c], gw[(size_t)c * NC + j], s);
    vb[j] = s;
}

// ---------------- v[b,s] = sum_j vb[j]*(style[b,j,s]-mean)*rstd -------------------
__global__ __launch_bounds__(256) void vrow_kernel(const float* __restrict__ style,
                                                   const float2* __restrict__ st,
                                                   const float* __restrict__ vb,
                                                   float* __restrict__ v) {
    int b = blockIdx.y;
    int s = blockIdx.x * 256 + threadIdx.x;
    const float* sb = style + (size_t)b * NC * NHW;
    float acc = 0.f;
    for (int j = 0; j < NC; j++) {
        float2 m = st[b * NC + j];
        acc = fmaf(vb[j], (sb[(size_t)j * NHW + s] - m.x) * m.y, acc);
    }
    v[b * NHW + s] = acc;
}

// ---------------- ob2[c] = sum_m o_w[c,m]*h_b[m] + o_b[c] ------------------------
__global__ __launch_bounds__(256) void ob2_kernel(const float* __restrict__ ow,
                                                  const float* __restrict__ hb,
                                                  const float* __restrict__ ob,
                                                  float* __restrict__ ob2) {
    int c = blockIdx.x * 256 + threadIdx.x;
    float s = ob[c];
    for (int m = 0; m < NC; m++) s = fmaf(ow[(size_t)c * NC + m], hb[m], s);
    ob2[c] = s;
}

// ---------------- sparse softmax with exact candidate recompute ------------------
// E is an int8-quantized int8-MMA approximation (decode step 0.8; combined noise
// ~0.38). Candidates = entries above approx-max - 16.3 (exact fp32 recompute via
// nCf . TTf). Band exp-sum only in (max-26, max-16.3].
__global__ __launch_bounds__(256) void softmax_sparse_kernel(
    const int8_t* __restrict__ Eq, const float* __restrict__ vrow,
    const float* __restrict__ nCf, const float* __restrict__ TTf,
    ushort* __restrict__ lidx, float* __restrict__ lw, int* __restrict__ lcnt)
{
    __shared__ float  s_nc[NC];
    __shared__ ushort s_idx[CC];
    __shared__ float  s_ex[CC];
    __shared__ int    wsum[8], wbase[8], s_n;
    const int b = blockIdx.y, q = blockIdx.x;
    const size_t rowid = (size_t)b * NHW + q;
    const size_t base  = rowid * NHW;
    const int tid = threadIdx.x, lane = tid & 31, w = tid >> 5;

    // load E row (16 s8 per thread) + v, decode, find approx max
    const int4* p = (const int4*)(Eq + base);
    int4 e4 = p[tid];
    const float4* vp = (const float4*)(vrow + (size_t)b * NHW) + tid * 4;
    float ev[16];
    {
        int wds[4] = {e4.x, e4.y, e4.z, e4.w};
        #pragma unroll
        for (int j = 0; j < 4; j++) {
            float4 vv = vp[j];
            int wd = wds[j];
            ev[4 * j + 0] = (float)((wd << 24) >> 24) * 0.8f + vv.x;
            ev[4 * j + 1] = (float)((wd << 16) >> 24) * 0.8f + vv.y;
            ev[4 * j + 2] = (float)((wd <<  8) >> 24) * 0.8f + vv.z;
            ev[4 * j + 3] = (float)( wd        >> 24) * 0.8f + vv.w;
        }
    }
    float mx = ev[0];
    #pragma unroll
    for (int j = 1; j < 16; j++) mx = fmaxf(mx, ev[j]);
    const float mxa = block_reduce_max(mx);
    const float T  = mxa - 16.3f;
    const float T2 = mxa - 26.0f;

    // load content row (fp32) into smem
    const float2* ncp = (const float2*)(nCf + rowid * NC);
    *(float2*)&s_nc[tid * 2] = ncp[tid];

    // candidate count + deterministic scan
    int cnt = 0;
    #pragma unroll
    for (int j = 0; j < 16; j++) cnt += (ev[j] > T);
    int incl = cnt;
    #pragma unroll
    for (int o = 1; o < 32; o <<= 1) {
        int n = __shfl_up_sync(0xffffffffu, incl, o);
        if (lane >= o) incl += n;
    }
    if (lane == 31) wsum[w] = incl;
    __syncthreads();
    if (tid == 0) {
        int r = 0;
        #pragma unroll
        for (int i = 0; i < 8; i++) { wbase[i] = r; r += wsum[i]; }
        s_n = (r < CC) ? r : CC;
    }
    __syncthreads();
    const int ncand = s_n;
    int k = wbase[w] + incl - cnt;

    // record candidate indices; band-limited non-candidate approx exp-sum
    float sn = 0.f;
    #pragma unroll
    for (int j = 0; j < 16; j++) {
        if (ev[j] > T) {
            if (k < CC) s_idx[k] = (ushort)(tid * 16 + j);
            k++;
        } else if (ev[j] > T2) {
            sn += __expf(ev[j] - mxa);
        }
    }
    const float Snon = block_reduce_sum(sn);

    // exact recompute: one warp per candidate
    for (int c = w; c < ncand; c += 8) {
        const int sidx = s_idx[c];
        const float4* tt = (const float4*)(TTf + ((size_t)b * NHW + sidx) * NC);
        float acc = 0.f;
        #pragma unroll
        for (int u = 0; u < 4; u++) {
            float4 t4 = tt[lane + 32 * u];
            const int o = (lane + 32 * u) * 4;
            acc = fmaf(t4.x, s_nc[o], acc);
            acc = fmaf(t4.y, s_nc[o + 1], acc);
            acc = fmaf(t4.z, s_nc[o + 2], acc);
            acc = fmaf(t4.w, s_nc[o + 3], acc);
        }
        #pragma unroll
        for (int o = 16; o > 0; o >>= 1) acc += __shfl_down_sync(0xffffffffu, acc, o);
        if (lane == 0) s_ex[c] = acc + vrow[(size_t)b * NHW + sidx];
    }
    __syncthreads();

    // denominator: banded non-candidates (approx) + candidates (exact)
    float cs = 0.f;
    for (int c = tid; c < ncand; c += 256) cs += __expf(s_ex[c] - mxa);
    const float Scand = block_reduce_sum(cs);
    const float inv = 1.0f / (Snon + Scand);

    // emit all candidates
    ushort* ip = lidx + rowid * CAP;
    float*  wp = lw   + rowid * CAP;
    for (int c = tid; c < ncand; c += 256) {
        ip[c] = s_idx[c];
        wp[c] = __expf(s_ex[c] - mxa) * inv;
    }
    if (tid == 0) lcnt[rowid] = ncand;
}

// ---------------- sparse apply: out[c,q] = ob2 + content + sum_k w*WoS[s_k,c] ----
__global__ __launch_bounds__(256) void sparse_apply_kernel(
    const float* __restrict__ WoS, const ushort* __restrict__ lidx,
    const float* __restrict__ lw, const int* __restrict__ lcnt,
    const float* __restrict__ ob2, const float* __restrict__ content,
    float* __restrict__ out)
{
    extern __shared__ float sacc[];   // [512][33]
    const int b = blockIdx.y, q0 = blockIdx.x * 32;
    const int tid = threadIdx.x, wid = tid >> 5, lane = tid & 31;
    const float* WoSb = WoS + (size_t)b * NHW * NC;

    #pragma unroll 1
    for (int j = 0; j < 4; j++) {
        const int q = q0 + wid * 4 + j;
        const size_t row = (size_t)b * NHW + q;
        const int cnt = lcnt[row];
        const ushort* ip = lidx + row * CAP;
        const float*  wp = lw   + row * CAP;
        float4 acc[4] = {};
        for (int k = 0; k < cnt; k++) {
            const int s = ip[k];
            const float wgt = wp[k];
            const float4* src = (const float4*)(WoSb + (size_t)s * NC) + lane;
            #pragma unroll
            for (int u = 0; u < 4; u++) {
                float4 vv = src[u * 32];
                acc[u].x = fmaf(wgt, vv.x, acc[u].x);
                acc[u].y = fmaf(wgt, vv.y, acc[u].y);
                acc[u].z = fmaf(wgt, vv.z, acc[u].z);
                acc[u].w = fmaf(wgt, vv.w, acc[u].w);
            }
        }
        const int qq = q - q0;
        #pragma unroll
        for (int u = 0; u < 4; u++) {
            const int c = lane * 4 + u * 128;
            sacc[(c + 0) * 33 + qq] = acc[u].x;
            sacc[(c + 1) * 33 + qq] = acc[u].y;
            sacc[(c + 2) * 33 + qq] = acc[u].z;
            sacc[(c + 3) * 33 + qq] = acc[u].w;
        }
    }
    __syncthreads();

    const float* cb = content + (size_t)b * NC * NHW;
    float* ob = out + (size_t)b * NC * NHW;
    #pragma unroll 1
    for (int p = 0; p < 16; p++) {
        const int c  = p * 32 + (tid >> 3);
        const int ch = (tid & 7) * 4;
        const float bias = ob2[c];
        float4 vv;
        vv.x = sacc[c * 33 + ch + 0] + bias;
        vv.y = sacc[c * 33 + ch + 1] + bias;
        vv.z = sacc[c * 33 + ch + 2] + bias;
        vv.w = sacc[c * 33 + ch + 3] + bias;
        const size_t o = (size_t)c * NHW + q0 + ch;
        const float4 cv = *(const float4*)(cb + o);
        vv.x += cv.x; vv.y += cv.y; vv.z += cv.z; vv.w += cv.w;
        *(float4*)(ob + o) = vv;
    }
}

// ---------------- 256x128 mma.sync GEMM ------------------------------------------
// NMMA 3: bf16 hi/lo 3-MMA split (K-step = 32 bf16 = 64B).
// NMMA 9: s8 single MMA m16n8k32, s32 accum (K-step = 64 s8 = 64B).
// SPLIT 4: merged N=1024: cols [0,512) -> Cf (WoS fp32); cols [512,1024) -> Cf2
//          (TTf fp32) + Cq (TT int8, scale 32). Output row stride = 512 each.
// SPLIT 5: C int8 via SMEM staging + coalesced copy (E screening, scale 1.25).
constexpr int ATB = 16384;           // 256 rows x 64B component
constexpr int BTB = 8192;            // 128 rows x 64B component
constexpr int NSTG = 3;
constexpr int STPAD = 144;           // staging row pitch (int8), 16B aligned

__device__ __forceinline__ uint32_t swz(int r, int c) {
    return (uint32_t)(r * 64 + ((c ^ ((r >> 1) & 3)) << 4));
}

template <int NMMA, int SPLIT>
__global__ __launch_bounds__(512, 1) void mma_gemm(
    const void* __restrict__ Ahi, const void* __restrict__ Alo,
    const void* __restrict__ Bhi, const void* __restrict__ Blo,
    float* __restrict__ Cf, float* __restrict__ Cf2,
    int8_t* __restrict__ Cq,
    int M, int N, int K,
    long sA, long sB, long sC)
{
    constexpr int ES     = (NMMA == 9) ? 1 : 2;
    constexpr int STGB   = (NMMA == 3) ? (2 * ATB + 2 * BTB) : (ATB + BTB);
    constexpr int OFF_BH = (NMMA == 3) ? 2 * ATB : ATB;

    extern __shared__ __align__(128) char dsm[];
    const uint32_t smb = s2u(dsm);

    const int tid = threadIdx.x, wid = tid >> 5, lane = tid & 31;
    const int m0 = blockIdx.y * 256, n0 = blockIdx.x * 128, b = blockIdx.z;
    const int warpM = wid & 3, warpN = wid >> 2;
    const int KT = (K * ES) / 64;          // K-steps of 64 bytes

    const int rA = tid >> 1, cA = (tid & 1) * 2;
    const int rB = tid >> 2, cB = tid & 3;
    const uint8_t* pAh = (const uint8_t*)Ahi + ((size_t)b * sA + (size_t)(m0 + rA) * K) * ES + cA * 16;
    const uint8_t* pAl = (NMMA == 3) ?
        (const uint8_t*)Alo + ((size_t)b * sA + (size_t)(m0 + rA) * K) * ES + cA * 16 : nullptr;
    const uint8_t* pBh = (const uint8_t*)Bhi + ((size_t)b * sB + (size_t)(n0 + rB) * K) * ES + cB * 16;
    const uint8_t* pBl = (NMMA == 3) ?
        (const uint8_t*)Blo + ((size_t)b * sB + (size_t)(n0 + rB) * K) * ES + cB * 16 : nullptr;
    const uint32_t dA0 = swz(rA, cA), dA1 = swz(rA, cA + 1);
    const uint32_t dB  = swz(rB, cB);

    auto load_stage = [&](int s, int k0b) {
        const uint32_t sb = smb + s * STGB;
        cpa16(sb + dA0, pAh + k0b);
        cpa16(sb + dA1, pAh + k0b + 16);
        if (NMMA == 3) {
            cpa16(sb + ATB + dA0, pAl + k0b);
            cpa16(sb + ATB + dA1, pAl + k0b + 16);
        }
        cpa16(sb + OFF_BH + dB, pBh + k0b);
        if (NMMA == 3) cpa16(sb + OFF_BH + BTB + dB, pBl + k0b);
    };

    float acc[4][4][4];
    #pragma unroll
    for (int i = 0; i < 4; i++)
        #pragma unroll
        for (int j = 0; j < 4; j++)
            #pragma unroll
            for (int q = 0; q < 4; q++) acc[i][j][q] = 0.f;   // 0.0f bits == int 0

    load_stage(0, 0);  cpa_commit();
    load_stage(1, 64); cpa_commit();

    const int arow = warpM * 64 + (lane & 15);
    const int brow = warpN * 32 + (lane & 15);

    for (int kt = 0; kt < KT; kt++) {
        cpa_wait1();
        __syncthreads();
        const int cur = kt % NSTG;
        if (kt + 2 < KT) load_stage((kt + 2) % NSTG, (kt + 2) * 64);
        cpa_commit();

        const uint32_t sAh = smb + cur * STGB;
        const uint32_t sAl = sAh + ATB;
        const uint32_t sBh = sAh + OFF_BH;
        const uint32_t sBl = sBh + BTB;

        #pragma unroll
        for (int kk = 0; kk < 2; kk++) {
            const int ch = kk * 2 + (lane >> 4);
            uint32_t ah[4][4], al[4][4];
            #pragma unroll
            for (int mi = 0; mi < 4; mi++) {
                uint32_t off = swz(arow + mi * 16, ch);
                ldsm4(sAh + off, ah[mi][0], ah[mi][1], ah[mi][2], ah[mi][3]);
                if (NMMA == 3)
                    ldsm4(sAl + off, al[mi][0], al[mi][1], al[mi][2], al[mi][3]);
            }
            #pragma unroll
            for (int g = 0; g < 2; g++) {
                uint32_t off = swz(brow + g * 16, ch);
                uint32_t h0, h1, h2, h3, l0, l1, l2, l3;
                ldsm4(sBh + off, h0, h1, h2, h3);
                if (NMMA == 3) ldsm4(sBl + off, l0, l1, l2, l3);
                #pragma unroll
                for (int mi = 0; mi < 4; mi++) {
                    if (NMMA == 9) {
                        mma_s8(acc[mi][2 * g],     ah[mi][0], ah[mi][1], ah[mi][2], ah[mi][3], h0, h2);
                        mma_s8(acc[mi][2 * g + 1], ah[mi][0], ah[mi][1], ah[mi][2], ah[mi][3], h1, h3);
                    } else {
                        mma_bf16(acc[mi][2 * g],     ah[mi][0], ah[mi][1], ah[mi][2], ah[mi][3], h0, h2);
                        mma_bf16(acc[mi][2 * g],     ah[mi][0], ah[mi][1], ah[mi][2], ah[mi][3], l0, l2);
                        mma_bf16(acc[mi][2 * g],     al[mi][0], al[mi][1], al[mi][2], al[mi][3], h0, h2);
                        mma_bf16(acc[mi][2 * g + 1], ah[mi][0], ah[mi][1], ah[mi][2], ah[mi][3], h1, h3);
                        mma_bf16(acc[mi][2 * g + 1], ah[mi][0], ah[mi][1], ah[mi][2], ah[mi][3], l1, l3);
                        mma_bf16(acc[mi][2 * g + 1], al[mi][0], al[mi][1], al[mi][2], al[mi][3], h1, h3);
                    }
                }
            }
        }
        __syncthreads();
    }

    // ---------------- epilogue -------------------------------------------------
    if (SPLIT == 5) {
        // stage int8 tile in (now free) pipeline smem, then coalesced copy out
        cpa_wait0();
        __syncthreads();
        char* stage = dsm;                 // 256 x STPAD bytes = 36 KB
        #pragma unroll
        for (int mi = 0; mi < 4; mi++) {
            const int rl0 = warpM * 64 + mi * 16 + (lane >> 2);
            #pragma unroll
            for (int j = 0; j < 4; j++) {
                const int cl = warpN * 32 + j * 8 + (lane & 3) * 2;
                int8_t a0 = to_s8E((float)(*(int*)&acc[mi][j][0]) * (1.f / 1024.f));
                int8_t a1 = to_s8E((float)(*(int*)&acc[mi][j][1]) * (1.f / 1024.f));
                *(ushort*)(stage + rl0 * STPAD + cl) =
                    (ushort)(uint8_t)a0 | ((ushort)(uint8_t)a1 << 8);
                a0 = to_s8E((float)(*(int*)&acc[mi][j][2]) * (1.f / 1024.f));
                a1 = to_s8E((float)(*(int*)&acc[mi][j][3]) * (1.f / 1024.f));
                *(ushort*)(stage + (rl0 + 8) * STPAD + cl) =
                    (ushort)(uint8_t)a0 | ((ushort)(uint8_t)a1 << 8);
            }
        }
        __syncthreads();
        // copy 256 rows x 128B; 2 threads per row, 64B each, fully coalesced
        const int r = tid >> 1, half = tid & 1;
        const int4* src = (const int4*)(stage + r * STPAD + half * 64);
        int4* dst = (int4*)(Cq + (size_t)b * sC + (size_t)(m0 + r) * N + n0 + half * 64);
        #pragma unroll
        for (int u = 0; u < 4; u++) dst[u] = src[u];
    } else {
        #pragma unroll
        for (int mi = 0; mi < 4; mi++) {
            const int r0 = m0 + warpM * 64 + mi * 16 + (lane >> 2);
            #pragma unroll
            for (int j = 0; j < 4; j++) {
                const int col = n0 + warpN * 32 + j * 8 + (lane & 3) * 2;
                float v[4] = {acc[mi][j][0], acc[mi][j][1], acc[mi][j][2], acc[mi][j][3]};
                // SPLIT == 4: merged output
                if (col < 512) {
                    const size_t o0 = (size_t)b * sC + (size_t)r0 * 512 + col;
                    const size_t o1 = o0 + (size_t)8 * 512;
                    *(float2*)(Cf + o0) = make_float2(v[0], v[1]);
                    *(float2*)(Cf + o1) = make_float2(v[2], v[3]);
                } else {
                    const int c2 = col - 512;
                    const size_t o0 = (size_t)b * sC + (size_t)r0 * 512 + c2;
                    const size_t o1 = o0 + (size_t)8 * 512;
                    *(float2*)(Cf2 + o0) = make_float2(v[0], v[1]);
                    *(float2*)(Cf2 + o1) = make_float2(v[2], v[3]);
                    uint8_t a0 = (uint8_t)to_s8(v[0]), a1 = (uint8_t)to_s8(v[1]);
                    *(ushort*)(Cq + o0) = (ushort)a0 | ((ushort)a1 << 8);
                    a0 = (uint8_t)to_s8(v[2]); a1 = (uint8_t)to_s8(v[3]);
                    *(ushort*)(Cq + o1) = (ushort)a0 | ((ushort)a1 << 8);
                }
            }
        }
    }
}

constexpr int DSMEM3 = NSTG * (2 * ATB + 2 * BTB);  // 144 KB
constexpr int DSMEM9 = NSTG * (ATB + BTB);          // 72 KB (>= 256*STPAD = 36 KB)

// ----------------------------- launch --------------------------------------------
extern "C" void kernel_launch(void* const* d_in, const int* in_sizes, int n_in,
                              void* d_out, int out_size) {
    const float* content = (const float*)d_in[0];
    const float* style   = (const float*)d_in[1];
    const float* f_w = (const float*)d_in[2];
    const float* f_b = (const float*)d_in[3];
    const float* g_w = (const float*)d_in[4];
    const float* h_w = (const float*)d_in[6];
    const float* h_b = (const float*)d_in[7];
    const float* o_w = (const float*)d_in[8];
    const float* o_b = (const float*)d_in[9];
    float* out = (float*)d_out;

    float *v, *vb, *ob2, *WoS, *lwp, *nCf, *TTf; float2 *stC, *stS;
    bf16 *sTh, *sTl, *W1h, *W1l, *Woh, *Wol, *Bh, *Bl;
    int8_t *E, *nCq, *TTq;
    ushort *lip; int *lcp;
    cudaGetSymbolAddress((void**)&E,   g_E);
    cudaGetSymbolAddress((void**)&v,   g_v);
    cudaGetSymbolAddress((void**)&vb,  g_vb);
    cudaGetSymbolAddress((void**)&ob2, g_ob2);
    cudaGetSymbolAddress((void**)&WoS, g_WoS);
    cudaGetSymbolAddress((void**)&stC, g_statC);
    cudaGetSymbolAddress((void**)&stS, g_statS);
    cudaGetSymbolAddress((void**)&nCq,  g_nCT_q);
    cudaGetSymbolAddress((void**)&nCf,  g_nCT_f);
    cudaGetSymbolAddress((void**)&sTh,  g_sT_h);  cudaGetSymbolAddress((void**)&sTl,  g_sT_l);
    cudaGetSymbolAddress((void**)&TTq,  g_TT_q);
    cudaGetSymbolAddress((void**)&TTf,  g_TT_f);
    cudaGetSymbolAddress((void**)&W1h,  g_W1_h);  cudaGetSymbolAddress((void**)&W1l,  g_W1_l);
    cudaGetSymbolAddress((void**)&Woh,  g_Wo_h);  cudaGetSymbolAddress((void**)&Wol,  g_Wo_l);
    cudaGetSymbolAddress((void**)&Bh,   g_Bs_h);  cudaGetSymbolAddress((void**)&Bl,   g_Bs_l);
    cudaGetSymbolAddress((void**)&lip,  g_lidx);
    cudaGetSymbolAddress((void**)&lwp,  g_lw);
    cudaGetSymbolAddress((void**)&lcp,  g_lcnt);

    cudaFuncSetAttribute(mma_gemm<3,4>, cudaFuncAttributeMaxDynamicSharedMemorySize, DSMEM3);
    cudaFuncSetAttribute(mma_gemm<9,5>, cudaFuncAttributeMaxDynamicSharedMemorySize, DSMEM9);
    cudaFuncSetAttribute(sparse_apply_kernel, cudaFuncAttributeMaxDynamicSharedMemorySize, 512 * 33 * 4);

    const long sQC = (long)NHW * NC;    // [B, 4096, 512]
    const long sBK = (long)2 * NC * NC; // stacked B per-batch stride (1024x512)
    const long sE  = (long)NHW * NHW;

    // 1) stats
    stats_kernel<<<NB * NC, 256>>>(content, stC);
    stats_kernel<<<NB * NC, 256>>>(style,   stS);

    // 2) transposed operands
    dim3 gt(NHW / 32, NC / 32, NB);
    tsplit_c_kernel<<<gt, 256>>>(content, stC, nCq, nCf);
    tsplit_raw_kernel<<<gt, 256>>>(style, sTh, sTl);

    // 3) folded weights: W1 = fw^T gw, Wo = o_w h_w; stacked B; bias vectors
    dim3 gw64(NC / 64, NC / 64);
    small_gemm_split<1><<<gw64, 256>>>(f_w, g_w, W1h, W1l);
    small_gemm_split<0><<<gw64, 256>>>(o_w, h_w, Woh, Wol);
    stack_kernel<<<(unsigned)((size_t)NB * 2 * NC * NC / 256), 256>>>(
        Woh, Wol, W1h, W1l, stS, Bh, Bl);
    vb_kernel<<<NC / 256, 256>>>(f_b, g_w, vb);
    vrow_kernel<<<dim3(NHW / 256, NB), 256>>>(style, stS, vb, v);
    ob2_kernel<<<NC / 256, 256>>>(o_w, h_b, o_b, ob2);

    // 4) merged: [WoS | TT] = sT x [Wo ; W1*rstd]^T  (M=4096, N=1024, K=512)
    dim3 gM(2 * NC / 128, NHW / 256, NB);   // (8, 16, 4)
    mma_gemm<3,4><<<gM, 512, DSMEM3>>>(sTh, sTl, Bh, Bl,
                                       WoS, TTf, TTq,
                                       NHW, 2 * NC, NC, sQC, sBK, sQC);

    // 5) E approx[q,s] (int8 1-MMA), int8 out via staged coalesced stores
    dim3 gE(NHW / 128, NHW / 256, NB);      // (32, 16, 4)
    mma_gemm<9,5><<<gE, 512, DSMEM9>>>(nCq, nullptr, TTq, nullptr,
                                       nullptr, nullptr, E,
                                       NHW, NHW, NC, sQC, sQC, sE);

    // 6) sparse softmax: candidates from approx E (int8), exact fp32 recompute
    dim3 gs(NHW, NB);
    softmax_sparse_kernel<<<gs, 256>>>(E, v, nCf, TTf, lip, lwp, lcp);

    // 7) sparse apply: out[c,q] = ob2[c] + content[c,q] + sum w * WoS[s,c]
    dim3 ga(NHW / 32, NB);
    sparse_apply_kernel<<<ga, 256, 512 * 33 * 4>>>(WoS, lip, lwp, lcp, ob2, content, out);
}